// round 1
// baseline (speedup 1.0000x reference)
#include <cuda_runtime.h>
#include <cuda_bf16.h>
#include <cstdint>

// Problem constants
#define BATCH 4
#define SEQ   2048
#define DMODEL 1024
#define NHEADS 16
#define HD    64
#define ROWS  (BATCH * SEQ)          // 8192
#define QKV_N (3 * DMODEL)           // 3072

// Scratch (allocation-free rule: __device__ globals)
__device__ float g_qkv[(size_t)ROWS * QKV_N];   // 25,165,824 floats
__device__ float g_att[(size_t)ROWS * DMODEL];  // 8,388,608 floats

// ---------------------------------------------------------------------------
// SGEMM: C[M,N] = A[M,K] @ B[K,N] (+ bias). Row-major. M,N,K multiples of 128/8.
// 128x128 block tile, BK=8, 256 threads, 8x8 microtile.
// ---------------------------------------------------------------------------
#define BM 128
#define BN 128
#define BK 8

__global__ void __launch_bounds__(256) sgemm_kernel(
    const float* __restrict__ A, const float* __restrict__ B,
    const float* __restrict__ bias, float* __restrict__ C,
    int M, int N, int K)
{
    __shared__ float As[BK][BM];
    __shared__ float Bs[BK][BN];

    const int tid  = threadIdx.x;
    const int brow = blockIdx.y;
    const int bcol = blockIdx.x;

    const float* Ab = A + (size_t)brow * BM * K;
    const float* Bb = B + (size_t)bcol * BN;

    // A tile load: 128 rows x 8 cols, one float4 per thread per iter (2 per row)
    const int arow = tid >> 1;
    const int acol = (tid & 1) * 4;
    // B tile load: 8 rows x 128 cols
    const int brl = tid >> 5;
    const int bcl = (tid & 31) * 4;

    const int ty = tid >> 4;   // 0..15
    const int tx = tid & 15;   // 0..15

    float acc[8][8];
    #pragma unroll
    for (int i = 0; i < 8; i++)
        #pragma unroll
        for (int j = 0; j < 8; j++) acc[i][j] = 0.f;

    for (int k0 = 0; k0 < K; k0 += BK) {
        float4 a4 = *(const float4*)(Ab + (size_t)arow * K + k0 + acol);
        As[acol + 0][arow] = a4.x;
        As[acol + 1][arow] = a4.y;
        As[acol + 2][arow] = a4.z;
        As[acol + 3][arow] = a4.w;
        float4 b4 = *(const float4*)(Bb + (size_t)(k0 + brl) * N + bcl);
        *(float4*)&Bs[brl][bcl] = b4;
        __syncthreads();

        #pragma unroll
        for (int k = 0; k < BK; k++) {
            float4 a0 = *(const float4*)&As[k][ty * 8];
            float4 a1 = *(const float4*)&As[k][ty * 8 + 4];
            float4 b0 = *(const float4*)&Bs[k][tx * 8];
            float4 b1 = *(const float4*)&Bs[k][tx * 8 + 4];
            float ar[8] = {a0.x, a0.y, a0.z, a0.w, a1.x, a1.y, a1.z, a1.w};
            float br[8] = {b0.x, b0.y, b0.z, b0.w, b1.x, b1.y, b1.z, b1.w};
            #pragma unroll
            for (int i = 0; i < 8; i++)
                #pragma unroll
                for (int j = 0; j < 8; j++) acc[i][j] += ar[i] * br[j];
        }
        __syncthreads();
    }

    const int crow0 = brow * BM + ty * 8;
    const int ccol0 = bcol * BN + tx * 8;
    #pragma unroll
    for (int i = 0; i < 8; i++) {
        float4 r0 = make_float4(acc[i][0], acc[i][1], acc[i][2], acc[i][3]);
        float4 r1 = make_float4(acc[i][4], acc[i][5], acc[i][6], acc[i][7]);
        if (bias) {
            float4 bb0 = *(const float4*)(bias + ccol0);
            float4 bb1 = *(const float4*)(bias + ccol0 + 4);
            r0.x += bb0.x; r0.y += bb0.y; r0.z += bb0.z; r0.w += bb0.w;
            r1.x += bb1.x; r1.y += bb1.y; r1.z += bb1.z; r1.w += bb1.w;
        }
        *(float4*)(C + (size_t)(crow0 + i) * N + ccol0)     = r0;
        *(float4*)(C + (size_t)(crow0 + i) * N + ccol0 + 4) = r1;
    }
}

// ---------------------------------------------------------------------------
// Flash attention, fp32, causal. 64 q-rows per block, 64-key tiles, Hd=64.
// 256 threads: thread (rq, cg) owns rows rq*4+{0..3}, cols cg+16*{0..3}
// (strided cols to keep shared-memory reads ~conflict-free).
// ---------------------------------------------------------------------------
#define FBM 64
#define FBN 64
#define LDP 68   // padded row stride in floats (68*4B, 16B-aligned rows)

__global__ void __launch_bounds__(256) flash_kernel(
    const float* __restrict__ qkv, float* __restrict__ out)
{
    extern __shared__ float sm[];
    float* Qs  = sm;                 // [64][LDP]
    float* Ks  = Qs  + FBM * LDP;    // [64][LDP]
    float* Vs  = Ks  + FBN * LDP;    // [64][LDP]
    float* PsT = Vs  + FBN * LDP;    // [64 cols][LDP rows-padded] transposed P

    const int tid = threadIdx.x;
    const int qt  = blockIdx.x;                // q-tile index (0..31)
    const int bh  = blockIdx.y;                // b*NHEADS + h
    const int b   = bh / NHEADS;
    const int h   = bh % NHEADS;

    const size_t rs = (size_t)QKV_N;           // qkv row stride = 3072
    const float* qb = qkv + ((size_t)b * SEQ) * rs + h * HD;
    const float* kb = qb + DMODEL;
    const float* vb = qb + 2 * DMODEL;
    const int q0 = qt * FBM;

    // load Q tile (64 rows x 64 floats) once
    for (int idx = tid; idx < FBM * 16; idx += 256) {
        int r = idx >> 4, c = (idx & 15) * 4;
        *(float4*)&Qs[r * LDP + c] = *(const float4*)(qb + (size_t)(q0 + r) * rs + c);
    }

    const int rq  = tid >> 4;      // 0..15
    const int cg  = tid & 15;      // 0..15
    const int rq4 = rq * 4;

    float o[4][4];
    #pragma unroll
    for (int i = 0; i < 4; i++)
        #pragma unroll
        for (int j = 0; j < 4; j++) o[i][j] = 0.f;
    float mrow[4] = {-1e30f, -1e30f, -1e30f, -1e30f};
    float lrow[4] = {0.f, 0.f, 0.f, 0.f};

    const float scale_log2e = 0.125f * 1.4426950408889634f;  // 1/sqrt(64)*log2(e)

    const int nkt = qt + 1;   // causal: only tiles with keys <= max query
    for (int kt = 0; kt < nkt; kt++) {
        // ---- load K,V tiles ----
        for (int idx = tid; idx < FBN * 16; idx += 256) {
            int r = idx >> 4, c = (idx & 15) * 4;
            const float* src = kb + (size_t)(kt * FBN + r) * rs + c;
            *(float4*)&Ks[r * LDP + c] = *(const float4*)src;
            *(float4*)&Vs[r * LDP + c] = *(const float4*)(src + DMODEL);
        }
        __syncthreads();

        // ---- S = Q @ K^T  (thread: 4 rows x 4 strided cols) ----
        float s[4][4];
        #pragma unroll
        for (int i = 0; i < 4; i++)
            #pragma unroll
            for (int j = 0; j < 4; j++) s[i][j] = 0.f;

        #pragma unroll
        for (int hd4 = 0; hd4 < 16; hd4++) {
            float4 q[4], k[4];
            #pragma unroll
            for (int i = 0; i < 4; i++)
                q[i] = *(const float4*)&Qs[(rq4 + i) * LDP + hd4 * 4];
            #pragma unroll
            for (int j = 0; j < 4; j++)
                k[j] = *(const float4*)&Ks[(cg + 16 * j) * LDP + hd4 * 4];
            #pragma unroll
            for (int i = 0; i < 4; i++)
                #pragma unroll
                for (int j = 0; j < 4; j++)
                    s[i][j] += q[i].x * k[j].x + q[i].y * k[j].y
                             + q[i].z * k[j].z + q[i].w * k[j].w;
        }

        // ---- causal mask (diagonal tile only) ----
        if (kt == qt) {
            #pragma unroll
            for (int i = 0; i < 4; i++) {
                int qidx = q0 + rq4 + i;
                #pragma unroll
                for (int j = 0; j < 4; j++) {
                    int kidx = kt * FBN + cg + 16 * j;
                    if (kidx > qidx) s[i][j] = -1e30f;
                }
            }
        }

        // ---- online softmax (per row; row-mates = 16 consecutive lanes) ----
        #pragma unroll
        for (int i = 0; i < 4; i++) {
            float t = s[i][0];
            t = fmaxf(t, s[i][1]); t = fmaxf(t, s[i][2]); t = fmaxf(t, s[i][3]);
            #pragma unroll
            for (int off = 1; off < 16; off <<= 1)
                t = fmaxf(t, __shfl_xor_sync(0xffffffffu, t, off));
            t *= scale_log2e;
            float mn = fmaxf(mrow[i], t);
            float alpha = exp2f(mrow[i] - mn);
            float ps = 0.f;
            #pragma unroll
            for (int j = 0; j < 4; j++) {
                float p = exp2f(s[i][j] * scale_log2e - mn);
                PsT[(cg + 16 * j) * LDP + rq4 + i] = p;
                ps += p;
            }
            #pragma unroll
            for (int off = 1; off < 16; off <<= 1)
                ps += __shfl_xor_sync(0xffffffffu, ps, off);
            lrow[i] = lrow[i] * alpha + ps;
            mrow[i] = mn;
            #pragma unroll
            for (int j = 0; j < 4; j++) o[i][j] *= alpha;
        }
        __syncthreads();   // PsT ready

        // ---- O += P @ V ----
        #pragma unroll 4
        for (int k = 0; k < FBN; k++) {
            float4 p4 = *(const float4*)&PsT[k * LDP + rq4];
            float v0 = Vs[k * LDP + cg];
            float v1 = Vs[k * LDP + cg + 16];
            float v2 = Vs[k * LDP + cg + 32];
            float v3 = Vs[k * LDP + cg + 48];
            o[0][0] += p4.x * v0; o[0][1] += p4.x * v1; o[0][2] += p4.x * v2; o[0][3] += p4.x * v3;
            o[1][0] += p4.y * v0; o[1][1] += p4.y * v1; o[1][2] += p4.y * v2; o[1][3] += p4.y * v3;
            o[2][0] += p4.z * v0; o[2][1] += p4.z * v1; o[2][2] += p4.z * v2; o[2][3] += p4.z * v3;
            o[3][0] += p4.w * v0; o[3][1] += p4.w * v1; o[3][2] += p4.w * v2; o[3][3] += p4.w * v3;
        }
        __syncthreads();   // PV done before K/V/PsT overwritten
    }

    // ---- epilogue: normalize and write [B,T,D] with head-major D ----
    #pragma unroll
    for (int i = 0; i < 4; i++) {
        float inv = 1.0f / lrow[i];
        size_t base = ((size_t)b * SEQ + q0 + rq4 + i) * DMODEL + h * HD;
        #pragma unroll
        for (int j = 0; j < 4; j++)
            out[base + cg + 16 * j] = o[i][j] * inv;
    }
}

// ---------------------------------------------------------------------------
extern "C" void kernel_launch(void* const* d_in, const int* in_sizes, int n_in,
                              void* d_out, int out_size)
{
    const float* x     = (const float*)d_in[0];   // [4,2048,1024]
    const float* w_qkv = (const float*)d_in[1];   // [1024,3072]
    const float* w_out = (const float*)d_in[2];   // [1024,1024]
    const float* b_out = (const float*)d_in[3];   // [1024]
    float* out = (float*)d_out;

    float *qkv, *att;
    cudaGetSymbolAddress((void**)&qkv, g_qkv);
    cudaGetSymbolAddress((void**)&att, g_att);

    // 1) QKV projection: [8192,1024] @ [1024,3072]
    {
        dim3 grid(QKV_N / BN, ROWS / BM);
        sgemm_kernel<<<grid, 256>>>(x, w_qkv, nullptr, qkv, ROWS, QKV_N, DMODEL);
    }

    // 2) Flash attention
    {
        size_t smem = (size_t)4 * 64 * LDP * sizeof(float);  // 69632 B
        cudaFuncSetAttribute(flash_kernel,
                             cudaFuncAttributeMaxDynamicSharedMemorySize, (int)smem);
        dim3 grid(SEQ / FBM, BATCH * NHEADS);
        flash_kernel<<<grid, 256, smem>>>(qkv, att);
    }

    // 3) Output projection + bias: [8192,1024] @ [1024,1024] + b
    {
        dim3 grid(DMODEL / BN, ROWS / BM);
        sgemm_kernel<<<grid, 256>>>(att, w_out, b_out, out, ROWS, DMODEL, DMODEL);
    }
}

// round 2
// speedup vs baseline: 1.7313x; 1.7313x over previous
#include <cuda_runtime.h>
#include <cuda_bf16.h>
#include <cstdint>

// Problem constants
#define BATCH 4
#define SEQ   2048
#define DMODEL 1024
#define NHEADS 16
#define HD    64
#define ROWS  (BATCH * SEQ)          // 8192
#define QKV_N (3 * DMODEL)           // 3072

// Scratch (allocation-free rule: __device__ globals)
__device__ float g_qkv[(size_t)ROWS * QKV_N];
__device__ float g_att[(size_t)ROWS * DMODEL];

// ---------------------------------------------------------------------------
// TF32 tensor-core GEMM: C[M,N] = A[M,K] @ B[K,N] (+bias), row-major.
// 128x128x16 block tile, 256 threads, warp grid 2x4, warp tile 64x32,
// mma.sync.m16n8k8.tf32. Shared layouts tuned for conflict-free frag loads.
// ---------------------------------------------------------------------------
#define BM 128
#define BN 128
#define BKK 16
#define AST 20    // As[m][k] row stride (floats): frag-load banks = 20r+c, conflict-free
#define BST 136   // Bs[k][n] row stride (floats): frag-load banks = 8c+r, conflict-free

__device__ __forceinline__ float to_tf32(float x) {
    uint32_t u;
    asm("cvt.rn.tf32.f32 %0, %1;" : "=r"(u) : "f"(x));
    return __uint_as_float(u);
}

__device__ __forceinline__ void mma_tf32(float& d0, float& d1, float& d2, float& d3,
                                         uint32_t a0, uint32_t a1, uint32_t a2, uint32_t a3,
                                         uint32_t b0, uint32_t b1)
{
    asm volatile(
        "mma.sync.aligned.m16n8k8.row.col.f32.tf32.tf32.f32 "
        "{%0,%1,%2,%3}, {%4,%5,%6,%7}, {%8,%9}, {%0,%1,%2,%3};"
        : "+f"(d0), "+f"(d1), "+f"(d2), "+f"(d3)
        : "r"(a0), "r"(a1), "r"(a2), "r"(a3), "r"(b0), "r"(b1));
}

__global__ void __launch_bounds__(256, 2) tf32_gemm_kernel(
    const float* __restrict__ A, const float* __restrict__ B,
    const float* __restrict__ bias, float* __restrict__ C,
    int M, int N, int K)
{
    __shared__ float As[BM][AST];   // [m][k], k in 0..15
    __shared__ float Bs[BKK][BST];  // [k][n]

    const int tid  = threadIdx.x;
    const int lane = tid & 31;
    const int warp = tid >> 5;

    const int brow = blockIdx.y;
    const int bcol = blockIdx.x;

    // loader indices
    const int am0 = tid >> 2;            // A: rows tid>>2 (+0), quad tid&3
    const int aq  = (tid & 3) * 4;
    const int bk0 = tid >> 5;            // B: two half-rows per thread
    const int bn0 = (tid & 31) * 4;

    // warp tiling: 2 rows x 4 cols
    const int wrow = warp >> 2;          // 0..1
    const int wcol = warp & 3;           // 0..3
    const int mbase = wrow * 64;
    const int nbase = wcol * 32;
    const int r = lane >> 2;             // 0..7
    const int c = lane & 3;              // 0..3

    const float* Ab = A + (size_t)brow * BM * K;
    const float* Bb = B + (size_t)bcol * BN;

    float acc[4][4][4];
    #pragma unroll
    for (int i = 0; i < 4; i++)
        #pragma unroll
        for (int j = 0; j < 4; j++)
            #pragma unroll
            for (int t = 0; t < 4; t++) acc[i][j][t] = 0.f;

    // software pipeline: prefetch global for iter 0
    float4 pa0 = *(const float4*)(Ab + (size_t)am0 * K + aq);
    float4 pa1 = *(const float4*)(Ab + (size_t)(am0 + 64) * K + aq);
    float4 pb0 = *(const float4*)(Bb + (size_t)bk0 * N + bn0);
    float4 pb1 = *(const float4*)(Bb + (size_t)(bk0 + 8) * N + bn0);

    for (int k0 = 0; k0 < K; k0 += BKK) {
        // store (tf32-rounded) tiles to shared
        *(float4*)&As[am0][aq] = make_float4(to_tf32(pa0.x), to_tf32(pa0.y),
                                             to_tf32(pa0.z), to_tf32(pa0.w));
        *(float4*)&As[am0 + 64][aq] = make_float4(to_tf32(pa1.x), to_tf32(pa1.y),
                                                  to_tf32(pa1.z), to_tf32(pa1.w));
        *(float4*)&Bs[bk0][bn0] = make_float4(to_tf32(pb0.x), to_tf32(pb0.y),
                                              to_tf32(pb0.z), to_tf32(pb0.w));
        *(float4*)&Bs[bk0 + 8][bn0] = make_float4(to_tf32(pb1.x), to_tf32(pb1.y),
                                                  to_tf32(pb1.z), to_tf32(pb1.w));
        __syncthreads();

        // prefetch next iter (overlaps with compute)
        if (k0 + BKK < K) {
            pa0 = *(const float4*)(Ab + (size_t)am0 * K + k0 + BKK + aq);
            pa1 = *(const float4*)(Ab + (size_t)(am0 + 64) * K + k0 + BKK + aq);
            pb0 = *(const float4*)(Bb + (size_t)(k0 + BKK + bk0) * N + bn0);
            pb1 = *(const float4*)(Bb + (size_t)(k0 + BKK + bk0 + 8) * N + bn0);
        }

        #pragma unroll
        for (int ks = 0; ks < 2; ks++) {
            const int kb = ks * 8;
            uint32_t af[4][4];
            #pragma unroll
            for (int mt = 0; mt < 4; mt++) {
                const int m = mbase + mt * 16;
                af[mt][0] = __float_as_uint(As[m + r][kb + c]);
                af[mt][1] = __float_as_uint(As[m + r + 8][kb + c]);
                af[mt][2] = __float_as_uint(As[m + r][kb + c + 4]);
                af[mt][3] = __float_as_uint(As[m + r + 8][kb + c + 4]);
            }
            uint32_t bf[4][2];
            #pragma unroll
            for (int nt = 0; nt < 4; nt++) {
                const int n = nbase + nt * 8 + r;
                bf[nt][0] = __float_as_uint(Bs[kb + c][n]);
                bf[nt][1] = __float_as_uint(Bs[kb + c + 4][n]);
            }
            #pragma unroll
            for (int mt = 0; mt < 4; mt++)
                #pragma unroll
                for (int nt = 0; nt < 4; nt++)
                    mma_tf32(acc[mt][nt][0], acc[mt][nt][1],
                             acc[mt][nt][2], acc[mt][nt][3],
                             af[mt][0], af[mt][1], af[mt][2], af[mt][3],
                             bf[nt][0], bf[nt][1]);
        }
        __syncthreads();
    }

    // epilogue: c0,c1 -> (row, 2c..2c+1); c2,c3 -> (row+8, 2c..2c+1)
    #pragma unroll
    for (int mt = 0; mt < 4; mt++) {
        const int row0 = brow * BM + mbase + mt * 16 + r;
        #pragma unroll
        for (int nt = 0; nt < 4; nt++) {
            const int col = bcol * BN + nbase + nt * 8 + 2 * c;
            float2 v0 = make_float2(acc[mt][nt][0], acc[mt][nt][1]);
            float2 v1 = make_float2(acc[mt][nt][2], acc[mt][nt][3]);
            if (bias) {
                float2 bb = *(const float2*)(bias + col);
                v0.x += bb.x; v0.y += bb.y;
                v1.x += bb.x; v1.y += bb.y;
            }
            *(float2*)(C + (size_t)row0 * N + col)       = v0;
            *(float2*)(C + (size_t)(row0 + 8) * N + col) = v1;
        }
    }
}

// ---------------------------------------------------------------------------
// Flash attention, fp32, causal (unchanged from round 1 — known good).
// ---------------------------------------------------------------------------
#define FBM 64
#define FBN 64
#define LDP 68

__global__ void __launch_bounds__(256) flash_kernel(
    const float* __restrict__ qkv, float* __restrict__ out)
{
    extern __shared__ float sm[];
    float* Qs  = sm;
    float* Ks  = Qs  + FBM * LDP;
    float* Vs  = Ks  + FBN * LDP;
    float* PsT = Vs  + FBN * LDP;

    const int tid = threadIdx.x;
    const int qt  = blockIdx.x;
    const int bh  = blockIdx.y;
    const int b   = bh / NHEADS;
    const int h   = bh % NHEADS;

    const size_t rs = (size_t)QKV_N;
    const float* qb = qkv + ((size_t)b * SEQ) * rs + h * HD;
    const float* kb = qb + DMODEL;
    const int q0 = qt * FBM;

    for (int idx = tid; idx < FBM * 16; idx += 256) {
        int r = idx >> 4, c2 = (idx & 15) * 4;
        *(float4*)&Qs[r * LDP + c2] = *(const float4*)(qb + (size_t)(q0 + r) * rs + c2);
    }

    const int rq  = tid >> 4;
    const int cg  = tid & 15;
    const int rq4 = rq * 4;

    float o[4][4];
    #pragma unroll
    for (int i = 0; i < 4; i++)
        #pragma unroll
        for (int j = 0; j < 4; j++) o[i][j] = 0.f;
    float mrow[4] = {-1e30f, -1e30f, -1e30f, -1e30f};
    float lrow[4] = {0.f, 0.f, 0.f, 0.f};

    const float scale_log2e = 0.125f * 1.4426950408889634f;

    const int nkt = qt + 1;
    for (int kt = 0; kt < nkt; kt++) {
        for (int idx = tid; idx < FBN * 16; idx += 256) {
            int r = idx >> 4, c2 = (idx & 15) * 4;
            const float* src = kb + (size_t)(kt * FBN + r) * rs + c2;
            *(float4*)&Ks[r * LDP + c2] = *(const float4*)src;
            *(float4*)&Vs[r * LDP + c2] = *(const float4*)(src + DMODEL);
        }
        __syncthreads();

        float s[4][4];
        #pragma unroll
        for (int i = 0; i < 4; i++)
            #pragma unroll
            for (int j = 0; j < 4; j++) s[i][j] = 0.f;

        #pragma unroll
        for (int hd4 = 0; hd4 < 16; hd4++) {
            float4 q[4], k[4];
            #pragma unroll
            for (int i = 0; i < 4; i++)
                q[i] = *(const float4*)&Qs[(rq4 + i) * LDP + hd4 * 4];
            #pragma unroll
            for (int j = 0; j < 4; j++)
                k[j] = *(const float4*)&Ks[(cg + 16 * j) * LDP + hd4 * 4];
            #pragma unroll
            for (int i = 0; i < 4; i++)
                #pragma unroll
                for (int j = 0; j < 4; j++)
                    s[i][j] += q[i].x * k[j].x + q[i].y * k[j].y
                             + q[i].z * k[j].z + q[i].w * k[j].w;
        }

        if (kt == qt) {
            #pragma unroll
            for (int i = 0; i < 4; i++) {
                int qidx = q0 + rq4 + i;
                #pragma unroll
                for (int j = 0; j < 4; j++) {
                    int kidx = kt * FBN + cg + 16 * j;
                    if (kidx > qidx) s[i][j] = -1e30f;
                }
            }
        }

        #pragma unroll
        for (int i = 0; i < 4; i++) {
            float t = s[i][0];
            t = fmaxf(t, s[i][1]); t = fmaxf(t, s[i][2]); t = fmaxf(t, s[i][3]);
            #pragma unroll
            for (int off = 1; off < 16; off <<= 1)
                t = fmaxf(t, __shfl_xor_sync(0xffffffffu, t, off));
            t *= scale_log2e;
            float mn = fmaxf(mrow[i], t);
            float alpha = exp2f(mrow[i] - mn);
            float ps = 0.f;
            #pragma unroll
            for (int j = 0; j < 4; j++) {
                float p = exp2f(s[i][j] * scale_log2e - mn);
                PsT[(cg + 16 * j) * LDP + rq4 + i] = p;
                ps += p;
            }
            #pragma unroll
            for (int off = 1; off < 16; off <<= 1)
                ps += __shfl_xor_sync(0xffffffffu, ps, off);
            lrow[i] = lrow[i] * alpha + ps;
            mrow[i] = mn;
            #pragma unroll
            for (int j = 0; j < 4; j++) o[i][j] *= alpha;
        }
        __syncthreads();

        #pragma unroll 4
        for (int k = 0; k < FBN; k++) {
            float4 p4 = *(const float4*)&PsT[k * LDP + rq4];
            float v0 = Vs[k * LDP + cg];
            float v1 = Vs[k * LDP + cg + 16];
            float v2 = Vs[k * LDP + cg + 32];
            float v3 = Vs[k * LDP + cg + 48];
            o[0][0] += p4.x * v0; o[0][1] += p4.x * v1; o[0][2] += p4.x * v2; o[0][3] += p4.x * v3;
            o[1][0] += p4.y * v0; o[1][1] += p4.y * v1; o[1][2] += p4.y * v2; o[1][3] += p4.y * v3;
            o[2][0] += p4.z * v0; o[2][1] += p4.z * v1; o[2][2] += p4.z * v2; o[2][3] += p4.z * v3;
            o[3][0] += p4.w * v0; o[3][1] += p4.w * v1; o[3][2] += p4.w * v2; o[3][3] += p4.w * v3;
        }
        __syncthreads();
    }

    #pragma unroll
    for (int i = 0; i < 4; i++) {
        float inv = 1.0f / lrow[i];
        size_t base = ((size_t)b * SEQ + q0 + rq4 + i) * DMODEL + h * HD;
        #pragma unroll
        for (int j = 0; j < 4; j++)
            out[base + cg + 16 * j] = o[i][j] * inv;
    }
}

// ---------------------------------------------------------------------------
extern "C" void kernel_launch(void* const* d_in, const int* in_sizes, int n_in,
                              void* d_out, int out_size)
{
    const float* x     = (const float*)d_in[0];
    const float* w_qkv = (const float*)d_in[1];
    const float* w_out = (const float*)d_in[2];
    const float* b_out = (const float*)d_in[3];
    float* out = (float*)d_out;

    float *qkv, *att;
    cudaGetSymbolAddress((void**)&qkv, g_qkv);
    cudaGetSymbolAddress((void**)&att, g_att);

    // 1) QKV projection: [8192,1024] @ [1024,3072]  (tf32 tensor cores)
    {
        dim3 grid(QKV_N / BN, ROWS / BM);
        tf32_gemm_kernel<<<grid, 256>>>(x, w_qkv, nullptr, qkv, ROWS, QKV_N, DMODEL);
    }

    // 2) Flash attention (fp32)
    {
        size_t smem = (size_t)4 * 64 * LDP * sizeof(float);
        cudaFuncSetAttribute(flash_kernel,
                             cudaFuncAttributeMaxDynamicSharedMemorySize, (int)smem);
        dim3 grid(SEQ / FBM, BATCH * NHEADS);
        flash_kernel<<<grid, 256, smem>>>(qkv, att);
    }

    // 3) Output projection + bias: [8192,1024] @ [1024,1024] + b
    {
        dim3 grid(DMODEL / BN, ROWS / BM);
        tf32_gemm_kernel<<<grid, 256>>>(att, w_out, b_out, out, ROWS, DMODEL, DMODEL);
    }
}

// round 3
// speedup vs baseline: 2.4235x; 1.3999x over previous
#include <cuda_runtime.h>
#include <cuda_bf16.h>
#include <cstdint>

// Problem constants
#define BATCH 4
#define SEQ   2048
#define DMODEL 1024
#define NHEADS 16
#define HD    64
#define ROWS  (BATCH * SEQ)          // 8192
#define QKV_N (3 * DMODEL)           // 3072

__device__ float g_qkv[(size_t)ROWS * QKV_N];
__device__ float g_att[(size_t)ROWS * DMODEL];

__device__ __forceinline__ uint32_t tf32u(float x) {
    uint32_t u;
    asm("cvt.rn.tf32.f32 %0, %1;" : "=r"(u) : "f"(x));
    return u;
}
__device__ __forceinline__ float tf32f(float x) { return __uint_as_float(tf32u(x)); }

__device__ __forceinline__ void mma_tf32(float& d0, float& d1, float& d2, float& d3,
                                         uint32_t a0, uint32_t a1, uint32_t a2, uint32_t a3,
                                         uint32_t b0, uint32_t b1)
{
    asm volatile(
        "mma.sync.aligned.m16n8k8.row.col.f32.tf32.tf32.f32 "
        "{%0,%1,%2,%3}, {%4,%5,%6,%7}, {%8,%9}, {%0,%1,%2,%3};"
        : "+f"(d0), "+f"(d1), "+f"(d2), "+f"(d3)
        : "r"(a0), "r"(a1), "r"(a2), "r"(a3), "r"(b0), "r"(b1));
}

// ---------------------------------------------------------------------------
// TF32 GEMM (unchanged from round 2 — 423us QKV, tensor=45%)
// ---------------------------------------------------------------------------
#define BM 128
#define BN 128
#define BKK 16
#define AST 20
#define BST 136

__global__ void __launch_bounds__(256, 2) tf32_gemm_kernel(
    const float* __restrict__ A, const float* __restrict__ B,
    const float* __restrict__ bias, float* __restrict__ C,
    int M, int N, int K)
{
    __shared__ float As[BM][AST];
    __shared__ float Bs[BKK][BST];

    const int tid  = threadIdx.x;
    const int lane = tid & 31;
    const int warp = tid >> 5;
    const int brow = blockIdx.y;
    const int bcol = blockIdx.x;

    const int am0 = tid >> 2;
    const int aq  = (tid & 3) * 4;
    const int bk0 = tid >> 5;
    const int bn0 = (tid & 31) * 4;

    const int wrow = warp >> 2;
    const int wcol = warp & 3;
    const int mbase = wrow * 64;
    const int nbase = wcol * 32;
    const int r = lane >> 2;
    const int c = lane & 3;

    const float* Ab = A + (size_t)brow * BM * K;
    const float* Bb = B + (size_t)bcol * BN;

    float acc[4][4][4];
    #pragma unroll
    for (int i = 0; i < 4; i++)
        #pragma unroll
        for (int j = 0; j < 4; j++)
            #pragma unroll
            for (int t = 0; t < 4; t++) acc[i][j][t] = 0.f;

    float4 pa0 = *(const float4*)(Ab + (size_t)am0 * K + aq);
    float4 pa1 = *(const float4*)(Ab + (size_t)(am0 + 64) * K + aq);
    float4 pb0 = *(const float4*)(Bb + (size_t)bk0 * N + bn0);
    float4 pb1 = *(const float4*)(Bb + (size_t)(bk0 + 8) * N + bn0);

    for (int k0 = 0; k0 < K; k0 += BKK) {
        *(float4*)&As[am0][aq] = make_float4(tf32f(pa0.x), tf32f(pa0.y), tf32f(pa0.z), tf32f(pa0.w));
        *(float4*)&As[am0 + 64][aq] = make_float4(tf32f(pa1.x), tf32f(pa1.y), tf32f(pa1.z), tf32f(pa1.w));
        *(float4*)&Bs[bk0][bn0] = make_float4(tf32f(pb0.x), tf32f(pb0.y), tf32f(pb0.z), tf32f(pb0.w));
        *(float4*)&Bs[bk0 + 8][bn0] = make_float4(tf32f(pb1.x), tf32f(pb1.y), tf32f(pb1.z), tf32f(pb1.w));
        __syncthreads();

        if (k0 + BKK < K) {
            pa0 = *(const float4*)(Ab + (size_t)am0 * K + k0 + BKK + aq);
            pa1 = *(const float4*)(Ab + (size_t)(am0 + 64) * K + k0 + BKK + aq);
            pb0 = *(const float4*)(Bb + (size_t)(k0 + BKK + bk0) * N + bn0);
            pb1 = *(const float4*)(Bb + (size_t)(k0 + BKK + bk0 + 8) * N + bn0);
        }

        #pragma unroll
        for (int ks = 0; ks < 2; ks++) {
            const int kb = ks * 8;
            uint32_t af[4][4];
            #pragma unroll
            for (int mt = 0; mt < 4; mt++) {
                const int m = mbase + mt * 16;
                af[mt][0] = __float_as_uint(As[m + r][kb + c]);
                af[mt][1] = __float_as_uint(As[m + r + 8][kb + c]);
                af[mt][2] = __float_as_uint(As[m + r][kb + c + 4]);
                af[mt][3] = __float_as_uint(As[m + r + 8][kb + c + 4]);
            }
            uint32_t bf[4][2];
            #pragma unroll
            for (int nt = 0; nt < 4; nt++) {
                const int n = nbase + nt * 8 + r;
                bf[nt][0] = __float_as_uint(Bs[kb + c][n]);
                bf[nt][1] = __float_as_uint(Bs[kb + c + 4][n]);
            }
            #pragma unroll
            for (int mt = 0; mt < 4; mt++)
                #pragma unroll
                for (int nt = 0; nt < 4; nt++)
                    mma_tf32(acc[mt][nt][0], acc[mt][nt][1],
                             acc[mt][nt][2], acc[mt][nt][3],
                             af[mt][0], af[mt][1], af[mt][2], af[mt][3],
                             bf[nt][0], bf[nt][1]);
        }
        __syncthreads();
    }

    #pragma unroll
    for (int mt = 0; mt < 4; mt++) {
        const int row0 = brow * BM + mbase + mt * 16 + r;
        #pragma unroll
        for (int nt = 0; nt < 4; nt++) {
            const int col = bcol * BN + nbase + nt * 8 + 2 * c;
            float2 v0 = make_float2(acc[mt][nt][0], acc[mt][nt][1]);
            float2 v1 = make_float2(acc[mt][nt][2], acc[mt][nt][3]);
            if (bias) {
                float2 bb = *(const float2*)(bias + col);
                v0.x += bb.x; v0.y += bb.y;
                v1.x += bb.x; v1.y += bb.y;
            }
            *(float2*)(C + (size_t)row0 * N + col)       = v0;
            *(float2*)(C + (size_t)(row0 + 8) * N + col) = v1;
        }
    }
}

// ---------------------------------------------------------------------------
// Tensor-core flash attention (tf32 mma), causal.
// CTA: 128 q-rows, 64-key tiles, 8 warps (warp w -> rows 16w..16w+15).
// S-phase uses Q = Qhi + Qlo split (2 mmas) for accuracy; PV single tf32.
// ---------------------------------------------------------------------------
#define FBM 128
#define FBN 64
#define QST 68   // Qh/Ql row stride: frag banks 4r+c, conflict-free
#define KST 68   // Ks row stride: b-frag banks 4r+c
#define VST 72   // Vs row stride: b-frag banks 8c+r, conflict-free
#define PST 68   // P  row stride: a-frag banks 4r+c

#define FLASH_SMEM ((2*FBM*QST + FBN*KST + FBN*VST + 8*16*PST) * 4)  // 140288 B

__global__ void __launch_bounds__(256, 1) flash_tc_kernel(
    const float* __restrict__ qkv, float* __restrict__ out)
{
    extern __shared__ float sm[];
    float* Qh = sm;
    float* Ql = Qh + FBM * QST;
    float* Ks = Ql + FBM * QST;
    float* Vs = Ks + FBN * KST;
    float* Ps = Vs + FBN * VST;

    const int tid  = threadIdx.x;
    const int lane = tid & 31;
    const int warp = tid >> 5;
    const int qt = (int)gridDim.x - 1 - (int)blockIdx.x;  // big blocks first
    const int bh = blockIdx.y;
    const int b  = bh >> 4;
    const int h  = bh & 15;

    const size_t rs = (size_t)QKV_N;
    const float* qb = qkv + (size_t)b * SEQ * rs + h * HD;
    const float* kb = qb + DMODEL;
    const int q0 = qt * FBM;

    // load Q tile: split into tf32 hi + lo
    for (int idx = tid; idx < FBM * 16; idx += 256) {
        int rr = idx >> 4, c4 = (idx & 15) * 4;
        float4 q = *(const float4*)(qb + (size_t)(q0 + rr) * rs + c4);
        float hx = tf32f(q.x), hy = tf32f(q.y), hz = tf32f(q.z), hw = tf32f(q.w);
        *(float4*)&Qh[rr * QST + c4] = make_float4(hx, hy, hz, hw);
        *(float4*)&Ql[rr * QST + c4] = make_float4(tf32f(q.x - hx), tf32f(q.y - hy),
                                                   tf32f(q.z - hz), tf32f(q.w - hw));
    }

    const int r = lane >> 2;
    const int c = lane & 3;
    const int m0 = warp * 16;
    float* Pw = Ps + warp * (16 * PST);

    float o[8][4];
    #pragma unroll
    for (int nt = 0; nt < 8; nt++)
        #pragma unroll
        for (int t = 0; t < 4; t++) o[nt][t] = 0.f;
    float mx0 = -1e30f, mx1 = -1e30f, l0 = 0.f, l1 = 0.f;
    const float sl2e = 0.125f * 1.4426950408889634f;

    const int nkt = 2 * qt + 2;
    for (int kt = 0; kt < nkt; kt++) {
        __syncthreads();   // previous iter's K/V readers done (also covers Q store on iter 0)
        for (int idx = tid; idx < FBN * 16; idx += 256) {
            int rr = idx >> 4, c4 = (idx & 15) * 4;
            const float* src = kb + (size_t)(kt * FBN + rr) * rs + c4;
            float4 k4 = *(const float4*)src;
            float4 v4 = *(const float4*)(src + DMODEL);
            *(float4*)&Ks[rr * KST + c4] = make_float4(tf32f(k4.x), tf32f(k4.y), tf32f(k4.z), tf32f(k4.w));
            Vs[rr * VST + c4 + 0] = tf32f(v4.x);
            Vs[rr * VST + c4 + 1] = tf32f(v4.y);
            Vs[rr * VST + c4 + 2] = tf32f(v4.z);
            Vs[rr * VST + c4 + 3] = tf32f(v4.w);
        }
        __syncthreads();

        // ---- S = Q @ K^T (16x64 per warp), Qhi+Qlo split ----
        float s[8][4];
        #pragma unroll
        for (int nt = 0; nt < 8; nt++)
            #pragma unroll
            for (int t = 0; t < 4; t++) s[nt][t] = 0.f;

        #pragma unroll
        for (int kc = 0; kc < 8; kc++) {
            const int k8 = kc * 8;
            uint32_t ah0 = __float_as_uint(Qh[(m0 + r) * QST + k8 + c]);
            uint32_t ah1 = __float_as_uint(Qh[(m0 + r + 8) * QST + k8 + c]);
            uint32_t ah2 = __float_as_uint(Qh[(m0 + r) * QST + k8 + c + 4]);
            uint32_t ah3 = __float_as_uint(Qh[(m0 + r + 8) * QST + k8 + c + 4]);
            uint32_t al0 = __float_as_uint(Ql[(m0 + r) * QST + k8 + c]);
            uint32_t al1 = __float_as_uint(Ql[(m0 + r + 8) * QST + k8 + c]);
            uint32_t al2 = __float_as_uint(Ql[(m0 + r) * QST + k8 + c + 4]);
            uint32_t al3 = __float_as_uint(Ql[(m0 + r + 8) * QST + k8 + c + 4]);
            #pragma unroll
            for (int nt = 0; nt < 8; nt++) {
                uint32_t b0 = __float_as_uint(Ks[(nt * 8 + r) * KST + k8 + c]);
                uint32_t b1 = __float_as_uint(Ks[(nt * 8 + r) * KST + k8 + c + 4]);
                mma_tf32(s[nt][0], s[nt][1], s[nt][2], s[nt][3], ah0, ah1, ah2, ah3, b0, b1);
                mma_tf32(s[nt][0], s[nt][1], s[nt][2], s[nt][3], al0, al1, al2, al3, b0, b1);
            }
        }

        // ---- causal mask (only the last two key tiles can cross the diagonal) ----
        if (kt >= 2 * qt) {
            const int q0i = q0 + m0 + r;
            #pragma unroll
            for (int nt = 0; nt < 8; nt++) {
                int k0i = kt * FBN + nt * 8 + 2 * c;
                if (k0i     > q0i)     s[nt][0] = -1e30f;
                if (k0i + 1 > q0i)     s[nt][1] = -1e30f;
                if (k0i     > q0i + 8) s[nt][2] = -1e30f;
                if (k0i + 1 > q0i + 8) s[nt][3] = -1e30f;
            }
        }

        // ---- online softmax: row r (frags 0,1) ----
        {
            float t = -1e30f;
            #pragma unroll
            for (int nt = 0; nt < 8; nt++) t = fmaxf(t, fmaxf(s[nt][0], s[nt][1]));
            t = fmaxf(t, __shfl_xor_sync(0xffffffffu, t, 1));
            t = fmaxf(t, __shfl_xor_sync(0xffffffffu, t, 2));
            t *= sl2e;
            float mn = fmaxf(mx0, t);
            float alpha = exp2f(mx0 - mn);
            float ps = 0.f;
            #pragma unroll
            for (int nt = 0; nt < 8; nt++) {
                float p0 = exp2f(s[nt][0] * sl2e - mn);
                float p1 = exp2f(s[nt][1] * sl2e - mn);
                s[nt][0] = p0; s[nt][1] = p1; ps += p0 + p1;
            }
            ps += __shfl_xor_sync(0xffffffffu, ps, 1);
            ps += __shfl_xor_sync(0xffffffffu, ps, 2);
            l0 = l0 * alpha + ps; mx0 = mn;
            #pragma unroll
            for (int nt = 0; nt < 8; nt++) { o[nt][0] *= alpha; o[nt][1] *= alpha; }
        }
        // ---- row r+8 (frags 2,3) ----
        {
            float t = -1e30f;
            #pragma unroll
            for (int nt = 0; nt < 8; nt++) t = fmaxf(t, fmaxf(s[nt][2], s[nt][3]));
            t = fmaxf(t, __shfl_xor_sync(0xffffffffu, t, 1));
            t = fmaxf(t, __shfl_xor_sync(0xffffffffu, t, 2));
            t *= sl2e;
            float mn = fmaxf(mx1, t);
            float alpha = exp2f(mx1 - mn);
            float ps = 0.f;
            #pragma unroll
            for (int nt = 0; nt < 8; nt++) {
                float p0 = exp2f(s[nt][2] * sl2e - mn);
                float p1 = exp2f(s[nt][3] * sl2e - mn);
                s[nt][2] = p0; s[nt][3] = p1; ps += p0 + p1;
            }
            ps += __shfl_xor_sync(0xffffffffu, ps, 1);
            ps += __shfl_xor_sync(0xffffffffu, ps, 2);
            l1 = l1 * alpha + ps; mx1 = mn;
            #pragma unroll
            for (int nt = 0; nt < 8; nt++) { o[nt][2] *= alpha; o[nt][3] *= alpha; }
        }

        // ---- P: C-frag -> warp-private smem -> A-frag (tf32-rounded) ----
        #pragma unroll
        for (int nt = 0; nt < 8; nt++) {
            const int col = nt * 8 + 2 * c;
            Pw[r * PST + col]           = __uint_as_float(tf32u(s[nt][0]));
            Pw[r * PST + col + 1]       = __uint_as_float(tf32u(s[nt][1]));
            Pw[(r + 8) * PST + col]     = __uint_as_float(tf32u(s[nt][2]));
            Pw[(r + 8) * PST + col + 1] = __uint_as_float(tf32u(s[nt][3]));
        }
        __syncwarp();

        // ---- O += P @ V ----
        #pragma unroll
        for (int kc = 0; kc < 8; kc++) {
            const int k8 = kc * 8;
            uint32_t a0 = __float_as_uint(Pw[r * PST + k8 + c]);
            uint32_t a1 = __float_as_uint(Pw[(r + 8) * PST + k8 + c]);
            uint32_t a2 = __float_as_uint(Pw[r * PST + k8 + c + 4]);
            uint32_t a3 = __float_as_uint(Pw[(r + 8) * PST + k8 + c + 4]);
            #pragma unroll
            for (int nt = 0; nt < 8; nt++) {
                uint32_t b0 = __float_as_uint(Vs[(k8 + c) * VST + nt * 8 + r]);
                uint32_t b1 = __float_as_uint(Vs[(k8 + c + 4) * VST + nt * 8 + r]);
                mma_tf32(o[nt][0], o[nt][1], o[nt][2], o[nt][3], a0, a1, a2, a3, b0, b1);
            }
        }
        __syncwarp();
    }

    // ---- epilogue ----
    const float inv0 = 1.f / l0;
    const float inv1 = 1.f / l1;
    const size_t row0 = (size_t)(b * SEQ + q0 + m0 + r) * DMODEL + h * HD;
    const size_t row1 = row0 + (size_t)8 * DMODEL;
    #pragma unroll
    for (int nt = 0; nt < 8; nt++) {
        const int col = nt * 8 + 2 * c;
        *(float2*)(out + row0 + col) = make_float2(o[nt][0] * inv0, o[nt][1] * inv0);
        *(float2*)(out + row1 + col) = make_float2(o[nt][2] * inv1, o[nt][3] * inv1);
    }
}

// ---------------------------------------------------------------------------
extern "C" void kernel_launch(void* const* d_in, const int* in_sizes, int n_in,
                              void* d_out, int out_size)
{
    const float* x     = (const float*)d_in[0];
    const float* w_qkv = (const float*)d_in[1];
    const float* w_out = (const float*)d_in[2];
    const float* b_out = (const float*)d_in[3];
    float* out = (float*)d_out;

    float *qkv, *att;
    cudaGetSymbolAddress((void**)&qkv, g_qkv);
    cudaGetSymbolAddress((void**)&att, g_att);

    // 1) QKV projection
    {
        dim3 grid(QKV_N / BN, ROWS / BM);
        tf32_gemm_kernel<<<grid, 256>>>(x, w_qkv, nullptr, qkv, ROWS, QKV_N, DMODEL);
    }

    // 2) Flash attention (tf32 tensor cores)
    {
        cudaFuncSetAttribute(flash_tc_kernel,
                             cudaFuncAttributeMaxDynamicSharedMemorySize, FLASH_SMEM);
        dim3 grid(SEQ / FBM, BATCH * NHEADS);
        flash_tc_kernel<<<grid, 256, FLASH_SMEM>>>(qkv, att);
    }

    // 3) Output projection + bias
    {
        dim3 grid(DMODEL / BN, ROWS / BM);
        tf32_gemm_kernel<<<grid, 256>>>(att, w_out, b_out, out, ROWS, DMODEL, DMODEL);
    }
}

// round 6
// speedup vs baseline: 3.0888x; 1.2745x over previous
#include <cuda_runtime.h>
#include <cuda_bf16.h>
#include <cstdint>

// Problem constants
#define BATCH 4
#define SEQ   2048
#define DMODEL 1024
#define NHEADS 16
#define HD    64
#define ROWS  (BATCH * SEQ)          // 8192
#define QKV_N (3 * DMODEL)           // 3072

// Scratch (allocation-free rule: __device__ globals)
__device__ float g_qkv[(size_t)ROWS * QKV_N];
__device__ float g_att[(size_t)ROWS * DMODEL];

// ---------------------------------------------------------------------------
// helpers
// ---------------------------------------------------------------------------
__device__ __forceinline__ uint32_t s2u(const void* p) {
    uint32_t a;
    asm("{ .reg .u64 t; cvta.to.shared.u64 t, %1; cvt.u32.u64 %0, t; }"
        : "=r"(a) : "l"(p));
    return a;
}
__device__ __forceinline__ uint32_t tf32u(float x) {
    uint32_t u; asm("cvt.rn.tf32.f32 %0, %1;" : "=r"(u) : "f"(x)); return u;
}
__device__ __forceinline__ float tf32f(float x) { return __uint_as_float(tf32u(x)); }

__device__ __forceinline__ void mma_tf32(float& d0, float& d1, float& d2, float& d3,
                                         uint32_t a0, uint32_t a1, uint32_t a2, uint32_t a3,
                                         uint32_t b0, uint32_t b1)
{
    asm volatile(
        "mma.sync.aligned.m16n8k8.row.col.f32.tf32.tf32.f32 "
        "{%0,%1,%2,%3}, {%4,%5,%6,%7}, {%8,%9}, {%0,%1,%2,%3};"
        : "+f"(d0), "+f"(d1), "+f"(d2), "+f"(d3)
        : "r"(a0), "r"(a1), "r"(a2), "r"(a3), "r"(b0), "r"(b1));
}

__device__ __forceinline__ void cpasync16(uint32_t dst, const void* src) {
    asm volatile("cp.async.cg.shared.global [%0], [%1], 16;" :: "r"(dst), "l"(src));
}
#define CP_COMMIT() asm volatile("cp.async.commit_group;" ::: "memory")
#define CP_WAIT0()  asm volatile("cp.async.wait_group 0;" ::: "memory")

// ---------------------------------------------------------------------------
// TF32 GEMM (round-2/3 kernel — 419us QKV, known good)
// ---------------------------------------------------------------------------
#define BM 128
#define BN 128
#define BKK 16
#define AST 20
#define BST 136

__global__ void __launch_bounds__(256, 2) tf32_gemm_kernel(
    const float* __restrict__ A, const float* __restrict__ B,
    const float* __restrict__ bias, float* __restrict__ C,
    int M, int N, int K)
{
    __shared__ float As[BM][AST];
    __shared__ float Bs[BKK][BST];

    const int tid  = threadIdx.x;
    const int lane = tid & 31;
    const int warp = tid >> 5;
    const int brow = blockIdx.y;
    const int bcol = blockIdx.x;

    const int am0 = tid >> 2;
    const int aq  = (tid & 3) * 4;
    const int bk0 = tid >> 5;
    const int bn0 = (tid & 31) * 4;

    const int wrow = warp >> 2;
    const int wcol = warp & 3;
    const int mbase = wrow * 64;
    const int nbase = wcol * 32;
    const int r = lane >> 2;
    const int c = lane & 3;

    const float* Ab = A + (size_t)brow * BM * K;
    const float* Bb = B + (size_t)bcol * BN;

    float acc[4][4][4];
    #pragma unroll
    for (int i = 0; i < 4; i++)
        #pragma unroll
        for (int j = 0; j < 4; j++)
            #pragma unroll
            for (int t = 0; t < 4; t++) acc[i][j][t] = 0.f;

    float4 pa0 = *(const float4*)(Ab + (size_t)am0 * K + aq);
    float4 pa1 = *(const float4*)(Ab + (size_t)(am0 + 64) * K + aq);
    float4 pb0 = *(const float4*)(Bb + (size_t)bk0 * N + bn0);
    float4 pb1 = *(const float4*)(Bb + (size_t)(bk0 + 8) * N + bn0);

    for (int k0 = 0; k0 < K; k0 += BKK) {
        *(float4*)&As[am0][aq] = make_float4(tf32f(pa0.x), tf32f(pa0.y), tf32f(pa0.z), tf32f(pa0.w));
        *(float4*)&As[am0 + 64][aq] = make_float4(tf32f(pa1.x), tf32f(pa1.y), tf32f(pa1.z), tf32f(pa1.w));
        *(float4*)&Bs[bk0][bn0] = make_float4(tf32f(pb0.x), tf32f(pb0.y), tf32f(pb0.z), tf32f(pb0.w));
        *(float4*)&Bs[bk0 + 8][bn0] = make_float4(tf32f(pb1.x), tf32f(pb1.y), tf32f(pb1.z), tf32f(pb1.w));
        __syncthreads();

        if (k0 + BKK < K) {
            pa0 = *(const float4*)(Ab + (size_t)am0 * K + k0 + BKK + aq);
            pa1 = *(const float4*)(Ab + (size_t)(am0 + 64) * K + k0 + BKK + aq);
            pb0 = *(const float4*)(Bb + (size_t)(k0 + BKK + bk0) * N + bn0);
            pb1 = *(const float4*)(Bb + (size_t)(k0 + BKK + bk0 + 8) * N + bn0);
        }

        #pragma unroll
        for (int ks = 0; ks < 2; ks++) {
            const int kb = ks * 8;
            uint32_t af[4][4];
            #pragma unroll
            for (int mt = 0; mt < 4; mt++) {
                const int m = mbase + mt * 16;
                af[mt][0] = __float_as_uint(As[m + r][kb + c]);
                af[mt][1] = __float_as_uint(As[m + r + 8][kb + c]);
                af[mt][2] = __float_as_uint(As[m + r][kb + c + 4]);
                af[mt][3] = __float_as_uint(As[m + r + 8][kb + c + 4]);
            }
            uint32_t bf[4][2];
            #pragma unroll
            for (int nt = 0; nt < 4; nt++) {
                const int n = nbase + nt * 8 + r;
                bf[nt][0] = __float_as_uint(Bs[kb + c][n]);
                bf[nt][1] = __float_as_uint(Bs[kb + c + 4][n]);
            }
            #pragma unroll
            for (int mt = 0; mt < 4; mt++)
                #pragma unroll
                for (int nt = 0; nt < 4; nt++)
                    mma_tf32(acc[mt][nt][0], acc[mt][nt][1],
                             acc[mt][nt][2], acc[mt][nt][3],
                             af[mt][0], af[mt][1], af[mt][2], af[mt][3],
                             bf[nt][0], bf[nt][1]);
        }
        __syncthreads();
    }

    #pragma unroll
    for (int mt = 0; mt < 4; mt++) {
        const int row0 = brow * BM + mbase + mt * 16 + r;
        #pragma unroll
        for (int nt = 0; nt < 4; nt++) {
            const int col = bcol * BN + nbase + nt * 8 + 2 * c;
            float2 v0 = make_float2(acc[mt][nt][0], acc[mt][nt][1]);
            float2 v1 = make_float2(acc[mt][nt][2], acc[mt][nt][3]);
            if (bias) {
                float2 bb = *(const float2*)(bias + col);
                v0.x += bb.x; v0.y += bb.y;
                v1.x += bb.x; v1.y += bb.y;
            }
            *(float2*)(C + (size_t)row0 * N + col)       = v0;
            *(float2*)(C + (size_t)(row0 + 8) * N + col) = v1;
        }
    }
}

// ---------------------------------------------------------------------------
// Flash attention v2 (tf32 mma), causal.
// vs round 3: P relayout via warp shuffles (no Ps smem), K/V via cp.async raw
// fp32 with cvt at fragment load, smem 140KB -> 103KB => 2 CTAs/SM.
// Numerics identical to round 3.
// ---------------------------------------------------------------------------
#define FBM 128
#define FBN 64
#define QST 68   // Qh/Ql row stride
#define KST 68   // Ks row stride (272B, 16B-aligned)
#define VST 72   // Vs row stride (288B, 16B-aligned)
#define FLASH_SMEM ((2*FBM*QST + FBN*KST + FBN*VST) * 4)   // 105472 B

__global__ void __launch_bounds__(256, 2) flash_tc_kernel(
    const float* __restrict__ qkv, float* __restrict__ out)
{
    extern __shared__ float sm[];
    float* Qh = sm;
    float* Ql = Qh + FBM * QST;
    float* Ks = Ql + FBM * QST;
    float* Vs = Ks + FBN * KST;

    const int tid  = threadIdx.x;
    const int lane = tid & 31;
    const int warp = tid >> 5;
    const int qt = (int)gridDim.x - 1 - (int)blockIdx.x;   // big blocks first
    const int bh = blockIdx.y;
    const int b  = bh >> 4;
    const int h  = bh & 15;

    const size_t rs = (size_t)QKV_N;
    const float* qb = qkv + (size_t)b * SEQ * rs + h * HD;
    const float* kb = qb + DMODEL;
    const int q0 = qt * FBM;

    // Q prologue: load, split to tf32 hi/lo, store to smem
    for (int idx = tid; idx < FBM * 16; idx += 256) {
        int rr = idx >> 4, c4 = (idx & 15) * 4;
        float4 q = *(const float4*)(qb + (size_t)(q0 + rr) * rs + c4);
        float hx = tf32f(q.x), hy = tf32f(q.y), hz = tf32f(q.z), hw = tf32f(q.w);
        *(float4*)&Qh[rr * QST + c4] = make_float4(hx, hy, hz, hw);
        *(float4*)&Ql[rr * QST + c4] = make_float4(tf32f(q.x - hx), tf32f(q.y - hy),
                                                   tf32f(q.z - hz), tf32f(q.w - hw));
    }

    const int r = lane >> 2;       // 0..7
    const int c = lane & 3;        // 0..3
    const int m0 = warp * 16;

    float o[8][4];
    #pragma unroll
    for (int nt = 0; nt < 8; nt++)
        #pragma unroll
        for (int t = 0; t < 4; t++) o[nt][t] = 0.f;
    float mx0 = -1e30f, mx1 = -1e30f, l0 = 0.f, l1 = 0.f;
    const float sl2e = 0.125f * 1.4426950408889634f;

    const int nkt = 2 * qt + 2;
    for (int kt = 0; kt < nkt; kt++) {
        __syncthreads();   // previous iter's K/V readers done (covers Q stores on iter 0)

        // K/V tile loads: raw fp32 via cp.async (2048 16B chunks / 256 threads)
        for (int idx = tid; idx < FBN * 16; idx += 256) {
            int rr = idx >> 4, ch = (idx & 15) * 4;
            const float* src = kb + (size_t)(kt * FBN + rr) * rs + ch;
            cpasync16(s2u(&Ks[rr * KST + ch]), src);
            cpasync16(s2u(&Vs[rr * VST + ch]), src + DMODEL);
        }
        CP_COMMIT();
        CP_WAIT0();
        __syncthreads();

        // ---- S = Q @ K^T (16x64 per warp), Qhi+Qlo split ----
        float s[8][4];
        #pragma unroll
        for (int nt = 0; nt < 8; nt++)
            #pragma unroll
            for (int t = 0; t < 4; t++) s[nt][t] = 0.f;

        #pragma unroll
        for (int kc = 0; kc < 8; kc++) {
            const int k8 = kc * 8;
            uint32_t ah0 = __float_as_uint(Qh[(m0 + r) * QST + k8 + c]);
            uint32_t ah1 = __float_as_uint(Qh[(m0 + r + 8) * QST + k8 + c]);
            uint32_t ah2 = __float_as_uint(Qh[(m0 + r) * QST + k8 + c + 4]);
            uint32_t ah3 = __float_as_uint(Qh[(m0 + r + 8) * QST + k8 + c + 4]);
            uint32_t al0 = __float_as_uint(Ql[(m0 + r) * QST + k8 + c]);
            uint32_t al1 = __float_as_uint(Ql[(m0 + r + 8) * QST + k8 + c]);
            uint32_t al2 = __float_as_uint(Ql[(m0 + r) * QST + k8 + c + 4]);
            uint32_t al3 = __float_as_uint(Ql[(m0 + r + 8) * QST + k8 + c + 4]);
            #pragma unroll
            for (int nt = 0; nt < 8; nt++) {
                uint32_t b0 = tf32u(Ks[(nt * 8 + r) * KST + k8 + c]);
                uint32_t b1 = tf32u(Ks[(nt * 8 + r) * KST + k8 + c + 4]);
                mma_tf32(s[nt][0], s[nt][1], s[nt][2], s[nt][3], ah0, ah1, ah2, ah3, b0, b1);
                mma_tf32(s[nt][0], s[nt][1], s[nt][2], s[nt][3], al0, al1, al2, al3, b0, b1);
            }
        }

        // ---- causal mask ----
        if (kt >= 2 * qt) {
            const int q0i = q0 + m0 + r;
            #pragma unroll
            for (int nt = 0; nt < 8; nt++) {
                int k0i = kt * FBN + nt * 8 + 2 * c;
                if (k0i     > q0i)     s[nt][0] = -1e30f;
                if (k0i + 1 > q0i)     s[nt][1] = -1e30f;
                if (k0i     > q0i + 8) s[nt][2] = -1e30f;
                if (k0i + 1 > q0i + 8) s[nt][3] = -1e30f;
            }
        }

        // ---- online softmax: row r (frags 0,1) ----
        {
            float t = -1e30f;
            #pragma unroll
            for (int nt = 0; nt < 8; nt++) t = fmaxf(t, fmaxf(s[nt][0], s[nt][1]));
            t = fmaxf(t, __shfl_xor_sync(0xffffffffu, t, 1));
            t = fmaxf(t, __shfl_xor_sync(0xffffffffu, t, 2));
            t *= sl2e;
            float mn = fmaxf(mx0, t);
            float alpha = exp2f(mx0 - mn);
            float ps = 0.f;
            #pragma unroll
            for (int nt = 0; nt < 8; nt++) {
                float p0 = exp2f(s[nt][0] * sl2e - mn);
                float p1 = exp2f(s[nt][1] * sl2e - mn);
                s[nt][0] = p0; s[nt][1] = p1; ps += p0 + p1;
            }
            ps += __shfl_xor_sync(0xffffffffu, ps, 1);
            ps += __shfl_xor_sync(0xffffffffu, ps, 2);
            l0 = l0 * alpha + ps; mx0 = mn;
            #pragma unroll
            for (int nt = 0; nt < 8; nt++) { o[nt][0] *= alpha; o[nt][1] *= alpha; }
        }
        // ---- row r+8 (frags 2,3) ----
        {
            float t = -1e30f;
            #pragma unroll
            for (int nt = 0; nt < 8; nt++) t = fmaxf(t, fmaxf(s[nt][2], s[nt][3]));
            t = fmaxf(t, __shfl_xor_sync(0xffffffffu, t, 1));
            t = fmaxf(t, __shfl_xor_sync(0xffffffffu, t, 2));
            t *= sl2e;
            float mn = fmaxf(mx1, t);
            float alpha = exp2f(mx1 - mn);
            float ps = 0.f;
            #pragma unroll
            for (int nt = 0; nt < 8; nt++) {
                float p0 = exp2f(s[nt][2] * sl2e - mn);
                float p1 = exp2f(s[nt][3] * sl2e - mn);
                s[nt][2] = p0; s[nt][3] = p1; ps += p0 + p1;
            }
            ps += __shfl_xor_sync(0xffffffffu, ps, 1);
            ps += __shfl_xor_sync(0xffffffffu, ps, 2);
            l1 = l1 * alpha + ps; mx1 = mn;
            #pragma unroll
            for (int nt = 0; nt < 8; nt++) { o[nt][2] *= alpha; o[nt][3] *= alpha; }
        }

        // ---- O += P @ V : P relayout C-frag -> A-frag via shuffles ----
        // P[r][k8+c] lives in lane 4r+(c>>1), element (c&1); (+4 col => lane+2)
        {
            const int src0 = 4 * r + (c >> 1);
            const int src1 = src0 + 2;
            const bool odd = (c & 1);
            #pragma unroll
            for (int kc = 0; kc < 8; kc++) {
                const int k8 = kc * 8;
                float t00 = __shfl_sync(0xffffffffu, s[kc][0], src0);
                float t01 = __shfl_sync(0xffffffffu, s[kc][1], src0);
                float t02 = __shfl_sync(0xffffffffu, s[kc][2], src0);
                float t03 = __shfl_sync(0xffffffffu, s[kc][3], src0);
                float t10 = __shfl_sync(0xffffffffu, s[kc][0], src1);
                float t11 = __shfl_sync(0xffffffffu, s[kc][1], src1);
                float t12 = __shfl_sync(0xffffffffu, s[kc][2], src1);
                float t13 = __shfl_sync(0xffffffffu, s[kc][3], src1);
                uint32_t a0 = tf32u(odd ? t01 : t00);
                uint32_t a1 = tf32u(odd ? t03 : t02);
                uint32_t a2 = tf32u(odd ? t11 : t10);
                uint32_t a3 = tf32u(odd ? t13 : t12);
                #pragma unroll
                for (int nt = 0; nt < 8; nt++) {
                    uint32_t b0 = tf32u(Vs[(k8 + c) * VST + nt * 8 + r]);
                    uint32_t b1 = tf32u(Vs[(k8 + c + 4) * VST + nt * 8 + r]);
                    mma_tf32(o[nt][0], o[nt][1], o[nt][2], o[nt][3], a0, a1, a2, a3, b0, b1);
                }
            }
        }
    }

    // ---- epilogue ----
    const float inv0 = 1.f / l0;
    const float inv1 = 1.f / l1;
    const size_t row0 = (size_t)(b * SEQ + q0 + m0 + r) * DMODEL + h * HD;
    const size_t row1 = row0 + (size_t)8 * DMODEL;
    #pragma unroll
    for (int nt = 0; nt < 8; nt++) {
        const int col = nt * 8 + 2 * c;
        *(float2*)(out + row0 + col) = make_float2(o[nt][0] * inv0, o[nt][1] * inv0);
        *(float2*)(out + row1 + col) = make_float2(o[nt][2] * inv1, o[nt][3] * inv1);
    }
}

// ---------------------------------------------------------------------------
extern "C" void kernel_launch(void* const* d_in, const int* in_sizes, int n_in,
                              void* d_out, int out_size)
{
    const float* x     = (const float*)d_in[0];
    const float* w_qkv = (const float*)d_in[1];
    const float* w_out = (const float*)d_in[2];
    const float* b_out = (const float*)d_in[3];
    float* out = (float*)d_out;

    float *qkv, *att;
    cudaGetSymbolAddress((void**)&qkv, g_qkv);
    cudaGetSymbolAddress((void**)&att, g_att);

    // 1) QKV projection (tf32 mma)
    {
        dim3 grid(QKV_N / BN, ROWS / BM);
        tf32_gemm_kernel<<<grid, 256>>>(x, w_qkv, nullptr, qkv, ROWS, QKV_N, DMODEL);
    }

    // 2) Flash attention v2 (tf32 mma, 2 CTAs/SM)
    {
        cudaFuncSetAttribute(flash_tc_kernel,
                             cudaFuncAttributeMaxDynamicSharedMemorySize, FLASH_SMEM);
        dim3 grid(SEQ / FBM, BATCH * NHEADS);
        flash_tc_kernel<<<grid, 256, FLASH_SMEM>>>(qkv, att);
    }

    // 3) Output projection + bias (tf32 mma)
    {
        dim3 grid(DMODEL / BN, ROWS / BM);
        tf32_gemm_kernel<<<grid, 256>>>(att, w_out, b_out, out, ROWS, DMODEL, DMODEL);
    }
}